// round 5
// baseline (speedup 1.0000x reference)
#include <cuda_runtime.h>

// ---------------------------------------------------------------------------
// AugNODE: y' = MLP([y, t]), RK4 with 8 fixed steps, y0 = [x, aug] (16384 x 64)
// Layers: 64->1024 (ReLU), 1024->1024 x3 (ReLU), 1024->64
// Strategy: fp32 smem-tiled SGEMM chain, fused bias + t*timecol + ReLU epilogue.
// Weights transposed once per launch into [K, N] for coalesced float4 loads.
// ---------------------------------------------------------------------------

#define BATCH 16384
#define VAR   64
#define HID   1024
#define OUTD  32

// -------------------- device scratch (no allocation allowed) ---------------
__device__ float g_Wk0[VAR * HID];   // [K=64,  N=1024]
__device__ float g_Wk1[HID * HID];   // [1024, 1024]
__device__ float g_Wk2[HID * HID];
__device__ float g_Wk3[HID * HID];
__device__ float g_Wk4[HID * VAR];   // [1024, 64]
__device__ float g_tc[5 * HID];      // per-layer time column (first N entries)
__device__ float g_actA[BATCH * HID];
__device__ float g_actB[BATCH * HID];
__device__ float g_y[BATCH * VAR];
__device__ float g_z[BATCH * VAR];
__device__ float g_kbuf[BATCH * VAR];
__device__ float g_acc[BATCH * VAR];

// -------------------- weight pack: W[N, K+1] -> Wk[K, N], tcol[N] ----------
__global__ void pack_kernel(const float* __restrict__ W, float* __restrict__ Wk,
                            float* __restrict__ tcol, int N, int K) {
    int idx = blockIdx.x * blockDim.x + threadIdx.x;
    if (idx < N * K) {
        int k = idx / N;
        int n = idx - k * N;
        Wk[idx] = W[n * (K + 1) + k];
    }
    if (idx < N) tcol[idx] = W[idx * (K + 1) + K];
}

// -------------------- y0 = concat(x, aug) ----------------------------------
__global__ void init_y_kernel(const float* __restrict__ x,
                              const float* __restrict__ aug,
                              float* __restrict__ y) {
    int i = blockIdx.x * blockDim.x + threadIdx.x;
    if (i < BATCH * VAR) {
        int b = i >> 6;
        int c = i & 63;
        y[i] = (c < 32) ? x[b * 32 + c] : aug[b * 32 + (c - 32)];
    }
}

// -------------------- dst = ca*a + cb*b ------------------------------------
__global__ void ew_kernel(float* __restrict__ dst, const float* __restrict__ a,
                          float ca, const float* __restrict__ b, float cb, int n) {
    int i = blockIdx.x * blockDim.x + threadIdx.x;
    if (i < n) dst[i] = fmaf(ca, a[i], cb * b[i]);
}

// -------------------- out[b, 0:32] = y[b, 0:32] ----------------------------
__global__ void copy_out_kernel(const float* __restrict__ y, float* __restrict__ out) {
    int i = blockIdx.x * blockDim.x + threadIdx.x;
    if (i < BATCH * OUTD) {
        int b = i / OUTD;
        int c = i - b * OUTD;
        out[i] = y[b * VAR + c];
    }
}

// -------------------- SGEMM: C[M,N] = A[M,K] * Bm[K,N] + bias + t*tcol -----
// A row-major [BATCH, K], Bm row-major [K, N].
template <int BM, int BN, int BK, int TM, int TN, bool RELU>
__global__ __launch_bounds__((BM / TM) * (BN / TN), 2)
void gemm_kernel(const float* __restrict__ A, const float* __restrict__ Bm,
                 const float* __restrict__ bias, const float* __restrict__ tcol,
                 float t, float* __restrict__ C, int N, int K) {
    constexpr int THREADS = (BM / TM) * (BN / TN);
    __shared__ float As[BK][BM];
    __shared__ float Bs[BK][BN];

    const int tid = threadIdx.x;
    const int bn  = blockIdx.x * BN;
    const int bm  = blockIdx.y * BM;
    const int tx  = tid % (BN / TN);
    const int ty  = tid / (BN / TN);

    float acc[TM][TN];
#pragma unroll
    for (int i = 0; i < TM; i++)
#pragma unroll
        for (int j = 0; j < TN; j++) acc[i][j] = 0.0f;

    const float* Aptr = A + (long)bm * K;
    const float* Bptr = Bm + bn;

    for (int k0 = 0; k0 < K; k0 += BK) {
        // Load A tile [BM, BK] (transposed into As[k][m]) via float4
        constexpr int A_LD = (BM * BK / 4) / THREADS;
#pragma unroll
        for (int i = 0; i < A_LD; i++) {
            int idx = tid + i * THREADS;
            int row = idx / (BK / 4);
            int c4  = idx % (BK / 4);
            const float4 v = *(const float4*)(Aptr + (long)row * K + k0 + c4 * 4);
            As[c4 * 4 + 0][row] = v.x;
            As[c4 * 4 + 1][row] = v.y;
            As[c4 * 4 + 2][row] = v.z;
            As[c4 * 4 + 3][row] = v.w;
        }
        // Load B tile [BK, BN] via float4
        constexpr int B_LD = (BK * BN / 4) / THREADS;
#pragma unroll
        for (int i = 0; i < B_LD; i++) {
            int idx = tid + i * THREADS;
            int row = idx / (BN / 4);
            int c4  = idx % (BN / 4);
            *(float4*)&Bs[row][c4 * 4] = *(const float4*)(Bptr + (long)(k0 + row) * N + c4 * 4);
        }
        __syncthreads();

#pragma unroll
        for (int kk = 0; kk < BK; kk++) {
            float a[TM], bf[TN];
#pragma unroll
            for (int i = 0; i < TM; i++) a[i] = As[kk][ty * TM + i];
#pragma unroll
            for (int j = 0; j < TN; j++) bf[j] = Bs[kk][tx * TN + j];
#pragma unroll
            for (int i = 0; i < TM; i++)
#pragma unroll
                for (int j = 0; j < TN; j++) acc[i][j] = fmaf(a[i], bf[j], acc[i][j]);
        }
        __syncthreads();
    }

    // Epilogue: + (bias + t * tcol), optional ReLU
    float add[TN];
#pragma unroll
    for (int j = 0; j < TN; j++) {
        int n = bn + tx * TN + j;
        add[j] = fmaf(t, tcol[n], bias[n]);
    }
#pragma unroll
    for (int i = 0; i < TM; i++) {
        long rowoff = (long)(bm + ty * TM + i) * N + bn + tx * TN;
#pragma unroll
        for (int j = 0; j < TN; j++) {
            float v = acc[i][j] + add[j];
            if (RELU) v = fmaxf(v, 0.0f);
            C[rowoff + j] = v;
        }
    }
}

// ---------------------------------------------------------------------------
extern "C" void kernel_launch(void* const* d_in, const int* in_sizes, int n_in,
                              void* d_out, int out_size) {
    (void)in_sizes; (void)n_in; (void)out_size;
    const float* x   = (const float*)d_in[0];
    const float* aug = (const float*)d_in[1];
    const float* W[5];
    const float* bi[5];
    for (int i = 0; i < 5; i++) {
        W[i]  = (const float*)d_in[2 + 2 * i];
        bi[i] = (const float*)d_in[3 + 2 * i];
    }
    float* out = (float*)d_out;

    float *Wk0, *Wk1, *Wk2, *Wk3, *Wk4, *tc, *actA, *actB, *y, *z, *kb, *acc;
    cudaGetSymbolAddress((void**)&Wk0, g_Wk0);
    cudaGetSymbolAddress((void**)&Wk1, g_Wk1);
    cudaGetSymbolAddress((void**)&Wk2, g_Wk2);
    cudaGetSymbolAddress((void**)&Wk3, g_Wk3);
    cudaGetSymbolAddress((void**)&Wk4, g_Wk4);
    cudaGetSymbolAddress((void**)&tc,  g_tc);
    cudaGetSymbolAddress((void**)&actA, g_actA);
    cudaGetSymbolAddress((void**)&actB, g_actB);
    cudaGetSymbolAddress((void**)&y,   g_y);
    cudaGetSymbolAddress((void**)&z,   g_z);
    cudaGetSymbolAddress((void**)&kb,  g_kbuf);
    cudaGetSymbolAddress((void**)&acc, g_acc);

    float* Wk[5]    = {Wk0, Wk1, Wk2, Wk3, Wk4};
    float* tcol[5]  = {tc, tc + HID, tc + 2 * HID, tc + 3 * HID, tc + 4 * HID};
    const int Ns[5] = {HID, HID, HID, HID, VAR};
    const int Ks[5] = {VAR, HID, HID, HID, HID};

    // Pack weights: W[N, K+1] -> [K, N] plus time column
    for (int i = 0; i < 5; i++) {
        int tot = Ns[i] * Ks[i];
        pack_kernel<<<(tot + 255) / 256, 256>>>(W[i], Wk[i], tcol[i], Ns[i], Ks[i]);
    }

    // y0 = [x, aug]
    init_y_kernel<<<(BATCH * VAR + 255) / 256, 256>>>(x, aug, y);

    const float dt    = 0.125f;
    const float halfd = 0.0625f;
    const float sixth = dt / 6.0f;
    const int   nEW   = BATCH * VAR;
    const int   gEW   = (nEW + 255) / 256;

    dim3 gMid(HID / 128, BATCH / 128);   // 1024->1024 and 64->1024 layers
    dim3 gLast(VAR / 64, BATCH / 128);   // 1024->64 layer

    // Evaluate f(t, in) -> kb using actA/actB ping-pong
    auto eval_f = [&](float t, const float* in) {
        gemm_kernel<128, 128, 16, 8, 8, true><<<gMid, 256>>>(in,   Wk[0], bi[0], tcol[0], t, actA, HID, VAR);
        gemm_kernel<128, 128, 16, 8, 8, true><<<gMid, 256>>>(actA, Wk[1], bi[1], tcol[1], t, actB, HID, HID);
        gemm_kernel<128, 128, 16, 8, 8, true><<<gMid, 256>>>(actB, Wk[2], bi[2], tcol[2], t, actA, HID, HID);
        gemm_kernel<128, 128, 16, 8, 8, true><<<gMid, 256>>>(actA, Wk[3], bi[3], tcol[3], t, actB, HID, HID);
        gemm_kernel<128, 64, 16, 8, 4, false><<<gLast, 256>>>(actB, Wk[4], bi[4], tcol[4], t, kb, VAR, HID);
    };

    for (int s = 0; s < 8; s++) {
        float t0 = (float)s * dt;

        eval_f(t0, y);                                                  // k1 -> kb
        ew_kernel<<<gEW, 256>>>(acc, kb, 1.0f, kb, 0.0f, nEW);          // acc = k1
        ew_kernel<<<gEW, 256>>>(z, y, 1.0f, kb, halfd, nEW);            // z = y + dt/2*k1

        eval_f(t0 + halfd, z);                                          // k2 -> kb
        ew_kernel<<<gEW, 256>>>(acc, acc, 1.0f, kb, 2.0f, nEW);         // acc += 2*k2
        ew_kernel<<<gEW, 256>>>(z, y, 1.0f, kb, halfd, nEW);            // z = y + dt/2*k2

        eval_f(t0 + halfd, z);                                          // k3 -> kb
        ew_kernel<<<gEW, 256>>>(acc, acc, 1.0f, kb, 2.0f, nEW);         // acc += 2*k3
        ew_kernel<<<gEW, 256>>>(z, y, 1.0f, kb, dt, nEW);               // z = y + dt*k3

        eval_f(t0 + dt, z);                                             // k4 -> kb
        ew_kernel<<<gEW, 256>>>(acc, acc, 1.0f, kb, 1.0f, nEW);         // acc += k4

        ew_kernel<<<gEW, 256>>>(y, y, 1.0f, acc, sixth, nEW);           // y += dt/6*acc
    }

    copy_out_kernel<<<(BATCH * OUTD + 255) / 256, 256>>>(y, out);
}

// round 6
// speedup vs baseline: 1.0011x; 1.0011x over previous
#include <cuda_runtime.h>

// ---------------------------------------------------------------------------
// AugNODE: y' = MLP([y, t]), RK4 with 8 fixed steps, y0 = [x, aug] (16384 x 64)
// Layers: 64->1024 (ReLU), 1024->1024 x3 (ReLU), 1024->64
// Strategy: fp32 smem-tiled SGEMM chain, fused bias + t*timecol + ReLU epilogue.
// Weights transposed once per launch into [K, N] for coalesced float4 loads.
// ---------------------------------------------------------------------------

#define BATCH 16384
#define VAR   64
#define HID   1024
#define OUTD  32

// -------------------- device scratch (no allocation allowed) ---------------
__device__ float g_Wk0[VAR * HID];   // [K=64,  N=1024]
__device__ float g_Wk1[HID * HID];   // [1024, 1024]
__device__ float g_Wk2[HID * HID];
__device__ float g_Wk3[HID * HID];
__device__ float g_Wk4[HID * VAR];   // [1024, 64]
__device__ float g_tc[5 * HID];      // per-layer time column (first N entries)
__device__ float g_actA[BATCH * HID];
__device__ float g_actB[BATCH * HID];
__device__ float g_y[BATCH * VAR];
__device__ float g_z[BATCH * VAR];
__device__ float g_kbuf[BATCH * VAR];
__device__ float g_acc[BATCH * VAR];

// -------------------- weight pack: W[N, K+1] -> Wk[K, N], tcol[N] ----------
__global__ void pack_kernel(const float* __restrict__ W, float* __restrict__ Wk,
                            float* __restrict__ tcol, int N, int K) {
    int idx = blockIdx.x * blockDim.x + threadIdx.x;
    if (idx < N * K) {
        int k = idx / N;
        int n = idx - k * N;
        Wk[idx] = W[n * (K + 1) + k];
    }
    if (idx < N) tcol[idx] = W[idx * (K + 1) + K];
}

// -------------------- y0 = concat(x, aug) ----------------------------------
__global__ void init_y_kernel(const float* __restrict__ x,
                              const float* __restrict__ aug,
                              float* __restrict__ y) {
    int i = blockIdx.x * blockDim.x + threadIdx.x;
    if (i < BATCH * VAR) {
        int b = i >> 6;
        int c = i & 63;
        y[i] = (c < 32) ? x[b * 32 + c] : aug[b * 32 + (c - 32)];
    }
}

// -------------------- dst = ca*a + cb*b ------------------------------------
__global__ void ew_kernel(float* __restrict__ dst, const float* __restrict__ a,
                          float ca, const float* __restrict__ b, float cb, int n) {
    int i = blockIdx.x * blockDim.x + threadIdx.x;
    if (i < n) dst[i] = fmaf(ca, a[i], cb * b[i]);
}

// -------------------- out[b, 0:32] = y[b, 0:32] ----------------------------
__global__ void copy_out_kernel(const float* __restrict__ y, float* __restrict__ out) {
    int i = blockIdx.x * blockDim.x + threadIdx.x;
    if (i < BATCH * OUTD) {
        int b = i / OUTD;
        int c = i - b * OUTD;
        out[i] = y[b * VAR + c];
    }
}

// -------------------- SGEMM: C[M,N] = A[M,K] * Bm[K,N] + bias + t*tcol -----
// A row-major [BATCH, K], Bm row-major [K, N].
template <int BM, int BN, int BK, int TM, int TN, bool RELU>
__global__ __launch_bounds__((BM / TM) * (BN / TN), 2)
void gemm_kernel(const float* __restrict__ A, const float* __restrict__ Bm,
                 const float* __restrict__ bias, const float* __restrict__ tcol,
                 float t, float* __restrict__ C, int N, int K) {
    constexpr int THREADS = (BM / TM) * (BN / TN);
    __shared__ float As[BK][BM];
    __shared__ float Bs[BK][BN];

    const int tid = threadIdx.x;
    const int bn  = blockIdx.x * BN;
    const int bm  = blockIdx.y * BM;
    const int tx  = tid % (BN / TN);
    const int ty  = tid / (BN / TN);

    float acc[TM][TN];
#pragma unroll
    for (int i = 0; i < TM; i++)
#pragma unroll
        for (int j = 0; j < TN; j++) acc[i][j] = 0.0f;

    const float* Aptr = A + (long)bm * K;
    const float* Bptr = Bm + bn;

    for (int k0 = 0; k0 < K; k0 += BK) {
        // Load A tile [BM, BK] (transposed into As[k][m]) via float4
        constexpr int A_LD = (BM * BK / 4) / THREADS;
#pragma unroll
        for (int i = 0; i < A_LD; i++) {
            int idx = tid + i * THREADS;
            int row = idx / (BK / 4);
            int c4  = idx % (BK / 4);
            const float4 v = *(const float4*)(Aptr + (long)row * K + k0 + c4 * 4);
            As[c4 * 4 + 0][row] = v.x;
            As[c4 * 4 + 1][row] = v.y;
            As[c4 * 4 + 2][row] = v.z;
            As[c4 * 4 + 3][row] = v.w;
        }
        // Load B tile [BK, BN] via float4
        constexpr int B_LD = (BK * BN / 4) / THREADS;
#pragma unroll
        for (int i = 0; i < B_LD; i++) {
            int idx = tid + i * THREADS;
            int row = idx / (BN / 4);
            int c4  = idx % (BN / 4);
            *(float4*)&Bs[row][c4 * 4] = *(const float4*)(Bptr + (long)(k0 + row) * N + c4 * 4);
        }
        __syncthreads();

#pragma unroll
        for (int kk = 0; kk < BK; kk++) {
            float a[TM], bf[TN];
#pragma unroll
            for (int i = 0; i < TM; i++) a[i] = As[kk][ty * TM + i];
#pragma unroll
            for (int j = 0; j < TN; j++) bf[j] = Bs[kk][tx * TN + j];
#pragma unroll
            for (int i = 0; i < TM; i++)
#pragma unroll
                for (int j = 0; j < TN; j++) acc[i][j] = fmaf(a[i], bf[j], acc[i][j]);
        }
        __syncthreads();
    }

    // Epilogue: + (bias + t * tcol), optional ReLU
    float add[TN];
#pragma unroll
    for (int j = 0; j < TN; j++) {
        int n = bn + tx * TN + j;
        add[j] = fmaf(t, tcol[n], bias[n]);
    }
#pragma unroll
    for (int i = 0; i < TM; i++) {
        long rowoff = (long)(bm + ty * TM + i) * N + bn + tx * TN;
#pragma unroll
        for (int j = 0; j < TN; j++) {
            float v = acc[i][j] + add[j];
            if (RELU) v = fmaxf(v, 0.0f);
            C[rowoff + j] = v;
        }
    }
}

// ---------------------------------------------------------------------------
extern "C" void kernel_launch(void* const* d_in, const int* in_sizes, int n_in,
                              void* d_out, int out_size) {
    (void)in_sizes; (void)n_in; (void)out_size;
    const float* x   = (const float*)d_in[0];
    const float* aug = (const float*)d_in[1];
    const float* W[5];
    const float* bi[5];
    for (int i = 0; i < 5; i++) {
        W[i]  = (const float*)d_in[2 + 2 * i];
        bi[i] = (const float*)d_in[3 + 2 * i];
    }
    float* out = (float*)d_out;

    float *Wk0, *Wk1, *Wk2, *Wk3, *Wk4, *tc, *actA, *actB, *y, *z, *kb, *acc;
    cudaGetSymbolAddress((void**)&Wk0, g_Wk0);
    cudaGetSymbolAddress((void**)&Wk1, g_Wk1);
    cudaGetSymbolAddress((void**)&Wk2, g_Wk2);
    cudaGetSymbolAddress((void**)&Wk3, g_Wk3);
    cudaGetSymbolAddress((void**)&Wk4, g_Wk4);
    cudaGetSymbolAddress((void**)&tc,  g_tc);
    cudaGetSymbolAddress((void**)&actA, g_actA);
    cudaGetSymbolAddress((void**)&actB, g_actB);
    cudaGetSymbolAddress((void**)&y,   g_y);
    cudaGetSymbolAddress((void**)&z,   g_z);
    cudaGetSymbolAddress((void**)&kb,  g_kbuf);
    cudaGetSymbolAddress((void**)&acc, g_acc);

    float* Wk[5]    = {Wk0, Wk1, Wk2, Wk3, Wk4};
    float* tcol[5]  = {tc, tc + HID, tc + 2 * HID, tc + 3 * HID, tc + 4 * HID};
    const int Ns[5] = {HID, HID, HID, HID, VAR};
    const int Ks[5] = {VAR, HID, HID, HID, HID};

    // Pack weights: W[N, K+1] -> [K, N] plus time column
    for (int i = 0; i < 5; i++) {
        int tot = Ns[i] * Ks[i];
        pack_kernel<<<(tot + 255) / 256, 256>>>(W[i], Wk[i], tcol[i], Ns[i], Ks[i]);
    }

    // y0 = [x, aug]
    init_y_kernel<<<(BATCH * VAR + 255) / 256, 256>>>(x, aug, y);

    const float dt    = 0.125f;
    const float halfd = 0.0625f;
    const float sixth = dt / 6.0f;
    const int   nEW   = BATCH * VAR;
    const int   gEW   = (nEW + 255) / 256;

    dim3 gMid(HID / 128, BATCH / 128);   // 1024->1024 and 64->1024 layers
    dim3 gLast(VAR / 64, BATCH / 128);   // 1024->64 layer

    // Evaluate f(t, in) -> kb using actA/actB ping-pong
    auto eval_f = [&](float t, const float* in) {
        gemm_kernel<128, 128, 16, 8, 8, true><<<gMid, 256>>>(in,   Wk[0], bi[0], tcol[0], t, actA, HID, VAR);
        gemm_kernel<128, 128, 16, 8, 8, true><<<gMid, 256>>>(actA, Wk[1], bi[1], tcol[1], t, actB, HID, HID);
        gemm_kernel<128, 128, 16, 8, 8, true><<<gMid, 256>>>(actB, Wk[2], bi[2], tcol[2], t, actA, HID, HID);
        gemm_kernel<128, 128, 16, 8, 8, true><<<gMid, 256>>>(actA, Wk[3], bi[3], tcol[3], t, actB, HID, HID);
        gemm_kernel<128, 64, 16, 8, 4, false><<<gLast, 256>>>(actB, Wk[4], bi[4], tcol[4], t, kb, VAR, HID);
    };

    for (int s = 0; s < 8; s++) {
        float t0 = (float)s * dt;

        eval_f(t0, y);                                                  // k1 -> kb
        ew_kernel<<<gEW, 256>>>(acc, kb, 1.0f, kb, 0.0f, nEW);          // acc = k1
        ew_kernel<<<gEW, 256>>>(z, y, 1.0f, kb, halfd, nEW);            // z = y + dt/2*k1

        eval_f(t0 + halfd, z);                                          // k2 -> kb
        ew_kernel<<<gEW, 256>>>(acc, acc, 1.0f, kb, 2.0f, nEW);         // acc += 2*k2
        ew_kernel<<<gEW, 256>>>(z, y, 1.0f, kb, halfd, nEW);            // z = y + dt/2*k2

        eval_f(t0 + halfd, z);                                          // k3 -> kb
        ew_kernel<<<gEW, 256>>>(acc, acc, 1.0f, kb, 2.0f, nEW);         // acc += 2*k3
        ew_kernel<<<gEW, 256>>>(z, y, 1.0f, kb, dt, nEW);               // z = y + dt*k3

        eval_f(t0 + dt, z);                                             // k4 -> kb
        ew_kernel<<<gEW, 256>>>(acc, acc, 1.0f, kb, 1.0f, nEW);         // acc += k4

        ew_kernel<<<gEW, 256>>>(y, y, 1.0f, acc, sixth, nEW);           // y += dt/6*acc
    }

    copy_out_kernel<<<(BATCH * OUTD + 255) / 256, 256>>>(y, out);
}

// round 8
// speedup vs baseline: 2.8605x; 2.8573x over previous
#include <cuda_runtime.h>
#include <cuda_bf16.h>
#include <cstdint>

#define BATCH 16384
#define VAR   64
#define HID   1024
#define OUTD  32

// -------------------- device scratch (no runtime allocation) ---------------
__device__ __align__(256) __nv_bfloat16 g_Whi0[HID*VAR],  g_Wlo0[HID*VAR];
__device__ __align__(256) __nv_bfloat16 g_Whi1[HID*HID],  g_Wlo1[HID*HID];
__device__ __align__(256) __nv_bfloat16 g_Whi2[HID*HID],  g_Wlo2[HID*HID];
__device__ __align__(256) __nv_bfloat16 g_Whi3[HID*HID],  g_Wlo3[HID*HID];
__device__ __align__(256) __nv_bfloat16 g_Whi4[VAR*HID],  g_Wlo4[VAR*HID];
__device__ __align__(256) float g_tc[5*HID];
__device__ __align__(256) __nv_bfloat16 g_aHiA[BATCH*HID], g_aLoA[BATCH*HID];
__device__ __align__(256) __nv_bfloat16 g_aHiB[BATCH*HID], g_aLoB[BATCH*HID];
__device__ __align__(256) __nv_bfloat16 g_yhi[BATCH*VAR],  g_ylo[BATCH*VAR];
__device__ __align__(256) __nv_bfloat16 g_zhi[BATCH*VAR],  g_zlo[BATCH*VAR];
__device__ __align__(256) float g_y[BATCH*VAR], g_kb[BATCH*VAR], g_acc[BATCH*VAR];

// ============================ PTX helpers (baseline ISA only) ==============
__device__ __forceinline__ uint32_t smem_u32(const void* p) {
    uint32_t a;
    asm("{ .reg .u64 t; cvta.to.shared.u64 t, %1; cvt.u32.u64 %0, t; }" : "=r"(a) : "l"(p));
    return a;
}
__device__ __forceinline__ void cp16(uint32_t dst, const void* src) {
    asm volatile("cp.async.cg.shared.global [%0], [%1], 16;" :: "r"(dst), "l"(src) : "memory");
}
__device__ __forceinline__ void cp_commit() {
    asm volatile("cp.async.commit_group;" ::: "memory");
}
template <int N>
__device__ __forceinline__ void cp_wait() {
    asm volatile("cp.async.wait_group %0;" :: "n"(N) : "memory");
}
__device__ __forceinline__ void ldmx4(uint32_t* r, uint32_t addr) {
    asm volatile("ldmatrix.sync.aligned.m8n8.x4.shared.b16 {%0,%1,%2,%3}, [%4];"
                 : "=r"(r[0]), "=r"(r[1]), "=r"(r[2]), "=r"(r[3]) : "r"(addr));
}
__device__ __forceinline__ void mma16816(float* d, const uint32_t* a, const uint32_t* b) {
    asm volatile(
        "mma.sync.aligned.m16n8k16.row.col.f32.bf16.bf16.f32 "
        "{%0,%1,%2,%3}, {%4,%5,%6,%7}, {%8,%9}, {%0,%1,%2,%3};"
        : "+f"(d[0]), "+f"(d[1]), "+f"(d[2]), "+f"(d[3])
        : "r"(a[0]), "r"(a[1]), "r"(a[2]), "r"(a[3]), "r"(b[0]), "r"(b[1]));
}
__device__ __forceinline__ uint32_t pk2(__nv_bfloat16 a, __nv_bfloat16 b) {
    return (uint32_t)__bfloat16_as_ushort(a) | ((uint32_t)__bfloat16_as_ushort(b) << 16);
}
__device__ __forceinline__ void st_hilo4(__nv_bfloat16* hi, __nv_bfloat16* lo,
                                         long i4, float4 v) {
    __nv_bfloat16 h0 = __float2bfloat16(v.x), h1 = __float2bfloat16(v.y);
    __nv_bfloat16 h2 = __float2bfloat16(v.z), h3 = __float2bfloat16(v.w);
    __nv_bfloat16 l0 = __float2bfloat16(v.x - __bfloat162float(h0));
    __nv_bfloat16 l1 = __float2bfloat16(v.y - __bfloat162float(h1));
    __nv_bfloat16 l2 = __float2bfloat16(v.z - __bfloat162float(h2));
    __nv_bfloat16 l3 = __float2bfloat16(v.w - __bfloat162float(h3));
    ((uint2*)hi)[i4] = make_uint2(pk2(h0, h1), pk2(h2, h3));
    ((uint2*)lo)[i4] = make_uint2(pk2(l0, l1), pk2(l2, l3));
}

// ======================== support kernels ==================================
__global__ void pack_w(const float* __restrict__ W, __nv_bfloat16* __restrict__ hi,
                       __nv_bfloat16* __restrict__ lo, float* __restrict__ tcol,
                       int N, int K) {
    int i = blockIdx.x * blockDim.x + threadIdx.x;
    if (i < N * K) {
        int n = i / K, k = i - n * K;
        float v = W[(long)n * (K + 1) + k];
        __nv_bfloat16 h = __float2bfloat16(v);
        hi[i] = h;
        lo[i] = __float2bfloat16(v - __bfloat162float(h));
    }
    if (i < N) tcol[i] = W[(long)i * (K + 1) + K];
}

__global__ void init_y(const float* __restrict__ x, const float* __restrict__ aug,
                       float* __restrict__ y, __nv_bfloat16* __restrict__ yhi,
                       __nv_bfloat16* __restrict__ ylo) {
    int i4 = blockIdx.x * blockDim.x + threadIdx.x;
    if (i4 >= BATCH * VAR / 4) return;
    int i = i4 * 4, b = i >> 6, c = i & 63;
    float4 v = (c < 32) ? ((const float4*)x)[(b * 32 + c) >> 2]
                        : ((const float4*)aug)[(b * 32 + (c - 32)) >> 2];
    ((float4*)y)[i4] = v;
    st_hilo4(yhi, ylo, i4, v);
}

// acc' = (mode ? acc : 0) + w*kb ; z = y + cz*kb -> zhi/zlo
__global__ void accz(const float* __restrict__ y, const float* __restrict__ kb,
                     float* __restrict__ acc, __nv_bfloat16* __restrict__ zhi,
                     __nv_bfloat16* __restrict__ zlo, float w, float cz, int mode) {
    int i4 = blockIdx.x * blockDim.x + threadIdx.x;
    if (i4 >= BATCH * VAR / 4) return;
    float4 k = ((const float4*)kb)[i4];
    float4 a;
    if (mode) {
        a = ((const float4*)acc)[i4];
        a.x = fmaf(w, k.x, a.x); a.y = fmaf(w, k.y, a.y);
        a.z = fmaf(w, k.z, a.z); a.w = fmaf(w, k.w, a.w);
    } else { a.x = w*k.x; a.y = w*k.y; a.z = w*k.z; a.w = w*k.w; }
    ((float4*)acc)[i4] = a;
    float4 yv = ((const float4*)y)[i4];
    float4 z;
    z.x = fmaf(cz, k.x, yv.x); z.y = fmaf(cz, k.y, yv.y);
    z.z = fmaf(cz, k.z, yv.z); z.w = fmaf(cz, k.w, yv.w);
    st_hilo4(zhi, zlo, i4, z);
}

__global__ void yupd(float* __restrict__ y, const float* __restrict__ acc,
                     const float* __restrict__ kb, __nv_bfloat16* __restrict__ yhi,
                     __nv_bfloat16* __restrict__ ylo, float sixth) {
    int i4 = blockIdx.x * blockDim.x + threadIdx.x;
    if (i4 >= BATCH * VAR / 4) return;
    float4 a = ((const float4*)acc)[i4];
    float4 k = ((const float4*)kb)[i4];
    float4 yv = ((float4*)y)[i4];
    yv.x = fmaf(sixth, a.x + k.x, yv.x);
    yv.y = fmaf(sixth, a.y + k.y, yv.y);
    yv.z = fmaf(sixth, a.z + k.z, yv.z);
    yv.w = fmaf(sixth, a.w + k.w, yv.w);
    ((float4*)y)[i4] = yv;
    st_hilo4(yhi, ylo, i4, yv);
}

__global__ void copy_out(const float* __restrict__ y, float* __restrict__ out) {
    int i = blockIdx.x * blockDim.x + threadIdx.x;
    if (i < BATCH * OUTD) {
        int b = i / OUTD, c = i - b * OUTD;
        out[i] = y[b * VAR + c];
    }
}

// =========================== mma.sync GEMM =================================
// C[BATCH,N] = A[BATCH,K] * B[N,K]^T + bias + t*tcol [+ReLU]
// A,B = bf16 hi/lo K-major planes. CTA tile 128 x BN, 8 warps (4x2),
// warp tile 32 x BN/2, mma m16n8k16, BK=32, cp.async double buffer.
template <int BN, bool RELU, bool OUTF32>
__global__ void __launch_bounds__(256, 2)
node_gemm(const __nv_bfloat16* __restrict__ Ahi, const __nv_bfloat16* __restrict__ Alo,
          const __nv_bfloat16* __restrict__ Bhi, const __nv_bfloat16* __restrict__ Blo,
          const float* __restrict__ bias, const float* __restrict__ tcol, float t,
          __nv_bfloat16* __restrict__ oHi, __nv_bfloat16* __restrict__ oLo,
          float* __restrict__ oF, int N, int K, int NC) {
    constexpr int STR   = 80;                 // smem row stride bytes (40 bf16)
    constexpr int A_BY  = 128 * STR;          // 10240
    constexpr int B_BY  = BN * STR;
    constexpr int STAGE = 2 * A_BY + 2 * B_BY;
    constexpr int NT    = BN / 16;            // n-tiles per warp (8 or 4)
    constexpr int PAIRS = NT / 2;
    constexpr int TOT   = 1024 + 8 * BN;      // cp16 ops per chunk
    constexpr int SP    = BN + 4;             // fp32 out-stage stride

    extern __shared__ char smem[];
    const uint32_t stg0 = smem_u32(smem);
    const int tid  = threadIdx.x;
    const int wid  = tid >> 5, lane = tid & 31;
    const int wm   = wid >> 1, wn = wid & 1;
    const int bn   = blockIdx.x * BN;
    const long m0  = (long)blockIdx.y * 128;

    const char* gA[2] = {(const char*)Ahi, (const char*)Alo};
    const char* gB[2] = {(const char*)Bhi, (const char*)Blo};
    const size_t rb = (size_t)K * 2;

    float acc[2][NT][4];
#pragma unroll
    for (int mt = 0; mt < 2; mt++)
#pragma unroll
        for (int nt = 0; nt < NT; nt++)
#pragma unroll
            for (int q = 0; q < 4; q++) acc[mt][nt][q] = 0.0f;

    // ---- issue one K-chunk of cp.async ----
    auto issue = [&](int c) {
        const uint32_t sbs = stg0 + (c & 1) * STAGE;
        const int k0b = c * 64;               // 32 bf16 = 64 bytes
#pragma unroll
        for (int it = 0; it < TOT / 256; it++) {
            int i = tid + it * 256;
            uint32_t dst; const char* src;
            if (i < 1024) {
                int pl = i >> 9, j = i & 511, r = j >> 2, q = j & 3;
                src = gA[pl] + (size_t)(m0 + r) * rb + k0b + q * 16;
                dst = sbs + pl * A_BY + r * STR + q * 16;
            } else {
                int ii = i - 1024;
                int pl = ii >= 4 * BN;
                int j = ii - pl * 4 * BN, r = j >> 2, q = j & 3;
                src = gB[pl] + (size_t)(bn + r) * rb + k0b + q * 16;
                dst = sbs + 2 * A_BY + pl * B_BY + r * STR + q * 16;
            }
            cp16(dst, src);
        }
        cp_commit();
    };

    // ldmatrix lane address components (constant across chunks)
    const int rowA  = wm * 32 + (lane & 15);            // + mt*16
    const int chA   = (lane >> 4) * 16;                 // k-chunk byte
    const int rowB  = wn * (BN / 2) + ((lane >> 4) & 1) * 8 + (lane & 7);  // + ntp*16
    const int chB   = ((lane >> 3) & 1) * 16;

    issue(0);
    for (int c = 0; c < NC; c++) {
        if (c + 1 < NC) { issue(c + 1); cp_wait<1>(); }
        else            { cp_wait<0>(); }
        __syncthreads();

        const uint32_t sbs = stg0 + (c & 1) * STAGE;
#pragma unroll
        for (int ks = 0; ks < 2; ks++) {
            uint32_t a[2][2][4];   // [plane][mt]
#pragma unroll
            for (int p = 0; p < 2; p++)
#pragma unroll
                for (int mt = 0; mt < 2; mt++)
                    ldmx4(a[p][mt], sbs + p * A_BY + (rowA + mt * 16) * STR + ks * 32 + chA);
#pragma unroll
            for (int ntp = 0; ntp < PAIRS; ntp++) {
                uint32_t bh[4], bl[4];
                uint32_t ba = sbs + 2 * A_BY + (rowB + ntp * 16) * STR + ks * 32 + chB;
                ldmx4(bh, ba);
                ldmx4(bl, ba + B_BY);
#pragma unroll
                for (int tt = 0; tt < 2; tt++) {
                    int nt = ntp * 2 + tt;
#pragma unroll
                    for (int mt = 0; mt < 2; mt++) {
                        mma16816(acc[mt][nt], a[0][mt], bh + 2 * tt);  // hi*hi
                        mma16816(acc[mt][nt], a[1][mt], bh + 2 * tt);  // lo*hi
                        mma16816(acc[mt][nt], a[0][mt], bl + 2 * tt);  // hi*lo
                    }
                }
            }
        }
        __syncthreads();
    }

    // ---- epilogue: acc -> fp32 smem stage -> bias/relu -> hi/lo (or fp32) ----
    float* stF = (float*)smem;
    {
        int r  = lane >> 2;
        int c2 = (lane & 3) * 2;
#pragma unroll
        for (int mt = 0; mt < 2; mt++)
#pragma unroll
            for (int nt = 0; nt < NT; nt++) {
                int row = wm * 32 + mt * 16 + r;
                int col = wn * (BN / 2) + nt * 8 + c2;
                stF[row * SP + col]           = acc[mt][nt][0];
                stF[row * SP + col + 1]       = acc[mt][nt][1];
                stF[(row + 8) * SP + col]     = acc[mt][nt][2];
                stF[(row + 8) * SP + col + 1] = acc[mt][nt][3];
            }
    }
    __syncthreads();

    constexpr int TASKS = 128 * (BN / 8);
#pragma unroll
    for (int it = 0; it < TASKS / 256; it++) {
        int id = tid + it * 256;
        int r = id / (BN / 8), ch = id % (BN / 8);
        int n0 = ch * 8;
        float v[8];
#pragma unroll
        for (int o = 0; o < 8; o++) {
            int n = bn + n0 + o;
            v[o] = stF[r * SP + n0 + o] + fmaf(t, tcol[n], bias[n]);
            if (RELU) v[o] = fmaxf(v[o], 0.0f);
        }
        long off = (m0 + r) * (long)N + bn + n0;
        if (OUTF32) {
            ((float4*)(oF + off))[0] = make_float4(v[0], v[1], v[2], v[3]);
            ((float4*)(oF + off))[1] = make_float4(v[4], v[5], v[6], v[7]);
        } else {
            uint32_t hp[4], lp[4];
#pragma unroll
            for (int q = 0; q < 4; q++) {
                __nv_bfloat16 h0 = __float2bfloat16(v[2*q]);
                __nv_bfloat16 h1 = __float2bfloat16(v[2*q+1]);
                hp[q] = pk2(h0, h1);
                lp[q] = pk2(__float2bfloat16(v[2*q]   - __bfloat162float(h0)),
                            __float2bfloat16(v[2*q+1] - __bfloat162float(h1)));
            }
            *(uint4*)(oHi + off) = make_uint4(hp[0], hp[1], hp[2], hp[3]);
            *(uint4*)(oLo + off) = make_uint4(lp[0], lp[1], lp[2], lp[3]);
        }
    }
}

// ---------------------------------------------------------------------------
extern "C" void kernel_launch(void* const* d_in, const int* in_sizes, int n_in,
                              void* d_out, int out_size) {
    (void)in_sizes; (void)n_in; (void)out_size;
    const float* x   = (const float*)d_in[0];
    const float* aug = (const float*)d_in[1];
    const float* W[5]; const float* bi[5];
    for (int i = 0; i < 5; i++) { W[i] = (const float*)d_in[2+2*i]; bi[i] = (const float*)d_in[3+2*i]; }
    float* out = (float*)d_out;

    __nv_bfloat16 *Whi[5], *Wlo[5], *aHiA, *aLoA, *aHiB, *aLoB, *yhi, *ylo, *zhi, *zlo;
    float *tc, *y, *kb, *acc;
    cudaGetSymbolAddress((void**)&Whi[0], g_Whi0); cudaGetSymbolAddress((void**)&Wlo[0], g_Wlo0);
    cudaGetSymbolAddress((void**)&Whi[1], g_Whi1); cudaGetSymbolAddress((void**)&Wlo[1], g_Wlo1);
    cudaGetSymbolAddress((void**)&Whi[2], g_Whi2); cudaGetSymbolAddress((void**)&Wlo[2], g_Wlo2);
    cudaGetSymbolAddress((void**)&Whi[3], g_Whi3); cudaGetSymbolAddress((void**)&Wlo[3], g_Wlo3);
    cudaGetSymbolAddress((void**)&Whi[4], g_Whi4); cudaGetSymbolAddress((void**)&Wlo[4], g_Wlo4);
    cudaGetSymbolAddress((void**)&tc,  g_tc);
    cudaGetSymbolAddress((void**)&aHiA, g_aHiA); cudaGetSymbolAddress((void**)&aLoA, g_aLoA);
    cudaGetSymbolAddress((void**)&aHiB, g_aHiB); cudaGetSymbolAddress((void**)&aLoB, g_aLoB);
    cudaGetSymbolAddress((void**)&yhi, g_yhi); cudaGetSymbolAddress((void**)&ylo, g_ylo);
    cudaGetSymbolAddress((void**)&zhi, g_zhi); cudaGetSymbolAddress((void**)&zlo, g_zlo);
    cudaGetSymbolAddress((void**)&y, g_y); cudaGetSymbolAddress((void**)&kb, g_kb);
    cudaGetSymbolAddress((void**)&acc, g_acc);

    // dynamic smem: 2 stages of (2*A + 2*B) planes
    constexpr int SM128 = 2 * (2 * 128 * 80 + 2 * 128 * 80);   // 81920
    constexpr int SM64  = 2 * (2 * 128 * 80 + 2 * 64 * 80);    // 61440
    cudaFuncSetAttribute(node_gemm<128, true,  false>,
                         cudaFuncAttributeMaxDynamicSharedMemorySize, SM128);
    cudaFuncSetAttribute(node_gemm<64,  false, true>,
                         cudaFuncAttributeMaxDynamicSharedMemorySize, SM64);

    float* tcol[5] = {tc, tc + HID, tc + 2*HID, tc + 3*HID, tc + 4*HID};
    const int Ns[5] = {HID, HID, HID, HID, VAR};
    const int Ks[5] = {VAR, HID, HID, HID, HID};
    for (int i = 0; i < 5; i++) {
        int tot = Ns[i] * Ks[i];
        pack_w<<<(tot + 255) / 256, 256>>>(W[i], Whi[i], Wlo[i], tcol[i], Ns[i], Ks[i]);
    }

    init_y<<<1024, 256>>>(x, aug, y, yhi, ylo);

    const float dt = 0.125f, halfd = 0.0625f, sixth = dt / 6.0f;
    dim3 gMid(HID / 128, BATCH / 128);   // (8, 128)
    dim3 gLast(1, BATCH / 128);

    auto eval_f = [&](float t, const __nv_bfloat16* inHi, const __nv_bfloat16* inLo) {
        node_gemm<128, true, false><<<gMid, 256, SM128>>>(
            inHi, inLo, Whi[0], Wlo[0], bi[0], tcol[0], t, aHiA, aLoA, nullptr, HID, VAR, 2);
        node_gemm<128, true, false><<<gMid, 256, SM128>>>(
            aHiA, aLoA, Whi[1], Wlo[1], bi[1], tcol[1], t, aHiB, aLoB, nullptr, HID, HID, 32);
        node_gemm<128, true, false><<<gMid, 256, SM128>>>(
            aHiB, aLoB, Whi[2], Wlo[2], bi[2], tcol[2], t, aHiA, aLoA, nullptr, HID, HID, 32);
        node_gemm<128, true, false><<<gMid, 256, SM128>>>(
            aHiA, aLoA, Whi[3], Wlo[3], bi[3], tcol[3], t, aHiB, aLoB, nullptr, HID, HID, 32);
        node_gemm<64, false, true><<<gLast, 256, SM64>>>(
            aHiB, aLoB, Whi[4], Wlo[4], bi[4], tcol[4], t, nullptr, nullptr, kb, VAR, HID, 32);
    };

    for (int s = 0; s < 8; s++) {
        float t0 = (float)s * dt;
        eval_f(t0, yhi, ylo);                                        // k1
        accz<<<1024, 256>>>(y, kb, acc, zhi, zlo, 1.0f, halfd, 0);   // acc=k1;  z=y+dt/2*k1
        eval_f(t0 + halfd, zhi, zlo);                                // k2
        accz<<<1024, 256>>>(y, kb, acc, zhi, zlo, 2.0f, halfd, 1);   // acc+=2k2; z=y+dt/2*k2
        eval_f(t0 + halfd, zhi, zlo);                                // k3
        accz<<<1024, 256>>>(y, kb, acc, zhi, zlo, 2.0f, dt, 1);      // acc+=2k3; z=y+dt*k3
        eval_f(t0 + dt, zhi, zlo);                                   // k4
        yupd<<<1024, 256>>>(y, acc, kb, yhi, ylo, sixth);            // y+=dt/6*(acc+k4)
    }

    copy_out<<<(BATCH * OUTD + 255) / 256, 256>>>(y, out);
}